// round 4
// baseline (speedup 1.0000x reference)
#include <cuda_runtime.h>

// ---------------------------------------------------------------------------
// WaveletConv in 3 launches:
//   fwd_fused : fwd levels 1-3 (halo recomputation, x -> lo3 + hi1..hi3)
//   mid_kernel: fwd 4-8 + inv 7-3 fused per-channel in smem
//   inv_fused : inv levels 2-0 (prev3 + hi3..hi1 -> out), 3 smem phases
// Packed f32x2 FMA throughout.
// ---------------------------------------------------------------------------

#define NCH      128
#define TLEN     131072
#define FNT      512    // mid kernel threads

// hi offsets padded to multiples of 4 floats (16B)
__device__ __constant__ int c_HOFF[8] = {0, 65540, 98312, 114700, 122896, 126996, 129048, 130076};
#define HI_STRIDE 130592

__device__ __constant__ float c_WLO[10] = {0.003335725285001549f, -0.012580751999015526f,
    -0.006241490213011705f, 0.07757149384006515f, -0.03224486958502952f,
    -0.24229488706619015f, 0.13842814590110342f, 0.7243085284385744f,
    0.6038292697974729f, 0.160102397974125f};
__device__ __constant__ float c_WHI[10] = {-0.160102397974125f, 0.6038292697974729f,
    -0.7243085284385744f, 0.13842814590110342f, 0.24229488706619015f,
    -0.03224486958502952f, -0.07757149384006515f, -0.006241490213011705f,
    0.012580751999015526f, 0.003335725285001549f};

// Static scratch (allocation-free rule)
__device__ __align__(16) float g_hi[NCH * HI_STRIDE];    // hi1..hi8
__device__ __align__(16) float g_bufB[NCH * 65540];      // lo3, then prev3

// ---- packed f32x2 helpers --------------------------------------------------
typedef unsigned long long ull;

__device__ __forceinline__ ull pk2(float lo, float hi) {
    ull r; asm("mov.b64 %0, {%1, %2};" : "=l"(r) : "f"(lo), "f"(hi)); return r;
}
__device__ __forceinline__ ull bcast2(float v) {
    ull r; asm("mov.b64 %0, {%1, %1};" : "=l"(r) : "f"(v)); return r;
}
__device__ __forceinline__ void ffma2(ull& d, ull a, ull b) {
    asm("fma.rn.f32x2 %0, %1, %2, %3;" : "=l"(d) : "l"(a), "l"(b), "l"(d));
}
__device__ __forceinline__ void add2(ull& d, ull a, ull b) {
    asm("add.rn.f32x2 %0, %1, %2;" : "=l"(d) : "l"(a), "l"(b));
}
__device__ __forceinline__ void unpk2(float& lo, float& hi, ull r) {
    asm("mov.b64 {%0, %1}, %2;" : "=f"(lo), "=f"(hi) : "l"(r));
}

// inverse compute: 4 consecutive t, packed even/odd outputs.
// sp2/sh2 are float2 views at buffer index (t_group_start - origin), where
// buffer[0] corresponds to global index (t_first_in_level - 7).
__device__ __forceinline__ void inv_compute4(const float2* sp2, const float2* sh2,
                                             const ull* PL, const ull* PH,
                                             ull* accp, ull* acch)
{
    #pragma unroll
    for (int k = 0; k < 4; k++) { accp[k] = 0ull; acch[k] = 0ull; }
    #pragma unroll
    for (int m = 0; m < 10; m++) {
        const float2 pv = sp2[m];
        const float2 hv = sh2[m];
        const ull pvx = bcast2(pv.x), pvy = bcast2(pv.y);
        const ull hvx = bcast2(hv.x), hvy = bcast2(hv.y);
        #pragma unroll
        for (int k = 0; k < 4; k++) {
            const int j0 = 2 * m - k;
            const int j1 = 2 * m + 1 - k;
            if (j0 >= 0 && j0 < 16) { ffma2(accp[k], pvx, PL[j0]); ffma2(acch[k], hvx, PH[j0]); }
            if (j1 >= 0 && j1 < 16) { ffma2(accp[k], pvy, PL[j1]); ffma2(acch[k], hvy, PH[j1]); }
        }
    }
}

__device__ __forceinline__ void fused_load_filters(
    const float* __restrict__ filt, int ch, int i, ull* PL, ull* PH)
{
    const float2* f2 = reinterpret_cast<const float2*>(filt + ((size_t)ch * 8 + (size_t)i) * 64);
    #pragma unroll
    for (int j = 0; j < 16; j++) {
        const float2 a = f2[j];
        const float2 b = f2[16 + j];
        PL[j] = pk2(a.y, a.x);
        PH[j] = pk2(b.y, b.x);
    }
}

// ---------------------------------------------------------------------------
// fwd_fused: levels 1-3. CTA owns lo3[c3, d3), recomputes lo1/lo2 with halo.
// Buffer convention: SB[q] = in[(2*a_out - 5) + q]; output n (rel r) reads
// float2 SB2[r+k] = taps (2k, 2k+1).
// ---------------------------------------------------------------------------
#define FW_D3  1024
#define FW_SX  8256   // >= szx max 8248
#define FW_SL1 4128   // >= sz1 max 4120
#define FW_SMEM ((FW_SX + FW_SL1) * 4)

__global__ void __launch_bounds__(256)
fwd_fused(const float* __restrict__ x)
{
    extern __shared__ __align__(16) float s[];
    float* SX  = s;             // x stage; later aliased by lo2
    float* SL1 = s + FW_SX;
    float* SL2 = s;             // alias (x dead after lvl1)

    const int ch = blockIdx.y, b = blockIdx.x, tid = threadIdx.x;
    const int L1 = 65537, L2 = 32769, L3 = 16385;

    const int c3 = b * FW_D3;
    if (c3 >= L3) return;
    const int d3  = min(c3 + FW_D3, L3);
    const int a2  = 2 * c3 - 5, sz2 = 2 * (d3 - c3) + 8;
    const int a1  = 2 * a2 - 5, sz1 = 2 * sz2 + 8;
    const int ax  = 2 * a1 - 5, szx = 2 * sz1 + 8;

    const float* __restrict__ xr = x + (size_t)ch * TLEN;

    for (int q = tid; q < szx; q += 256) {
        const int g = ax + q;
        SX[q] = ((unsigned)g < (unsigned)TLEN) ? xr[g] : 0.0f;
    }
    __syncthreads();

    ull W2[10];
    #pragma unroll
    for (int k = 0; k < 10; k++) W2[k] = pk2(c_WLO[k], c_WHI[k]);

    // ---- level 1: SX -> SL1 (lo), hi1 -> global (owned range only) ----
    {
        float* __restrict__ hi1 = g_hi + (size_t)ch * HI_STRIDE + 0;
        const int hlo = 4 * c3;
        const int hhi = min(4 * (c3 + FW_D3), L1);
        const float2* SB2 = reinterpret_cast<const float2*>(SX);
        for (int n = a1 + tid; n < a1 + sz1; n += 256) {
            const int r = n - a1;
            ull acc = 0ull;
            #pragma unroll
            for (int k = 0; k < 5; k++) {
                const float2 v = SB2[r + k];
                ffma2(acc, bcast2(v.x), W2[2 * k]);
                ffma2(acc, bcast2(v.y), W2[2 * k + 1]);
            }
            float alo, ahi; unpk2(alo, ahi, acc);
            const bool valid = (unsigned)n < (unsigned)L1;
            SL1[r] = valid ? alo : 0.0f;
            if (valid && n >= hlo && n < hhi) hi1[n] = ahi;
        }
    }
    __syncthreads();

    // ---- level 2: SL1 -> SL2 (aliases SX), hi2 -> global ----
    {
        float* __restrict__ hi2 = g_hi + (size_t)ch * HI_STRIDE + c_HOFF[1];
        const int hlo = 2 * c3;
        const int hhi = min(2 * (c3 + FW_D3), L2);
        const float2* SB2 = reinterpret_cast<const float2*>(SL1);
        for (int n = a2 + tid; n < a2 + sz2; n += 256) {
            const int r = n - a2;
            ull acc = 0ull;
            #pragma unroll
            for (int k = 0; k < 5; k++) {
                const float2 v = SB2[r + k];
                ffma2(acc, bcast2(v.x), W2[2 * k]);
                ffma2(acc, bcast2(v.y), W2[2 * k + 1]);
            }
            float alo, ahi; unpk2(alo, ahi, acc);
            const bool valid = (unsigned)n < (unsigned)L2;
            SL2[r] = valid ? alo : 0.0f;
            if (valid && n >= hlo && n < hhi) hi2[n] = ahi;
        }
    }
    __syncthreads();

    // ---- level 3: SL2 -> lo3 + hi3 global ----
    {
        float* __restrict__ lo3 = g_bufB + (size_t)ch * 65540;
        float* __restrict__ hi3 = g_hi + (size_t)ch * HI_STRIDE + c_HOFF[2];
        const float2* SB2 = reinterpret_cast<const float2*>(SL2);
        for (int j = c3 + tid; j < d3; j += 256) {
            const int r = j - c3;
            ull acc = 0ull;
            #pragma unroll
            for (int k = 0; k < 5; k++) {
                const float2 v = SB2[r + k];
                ffma2(acc, bcast2(v.x), W2[2 * k]);
                ffma2(acc, bcast2(v.y), W2[2 * k + 1]);
            }
            float alo, ahi; unpk2(alo, ahi, acc);
            lo3[j] = alo;
            hi3[j] = ahi;
        }
    }
}

// ---------------------------------------------------------------------------
// inv_fused: inverse levels 2..0. CTA owns out[4096b, 4096(b+1)).
// ---------------------------------------------------------------------------
#define IV_S3 548
#define IV_S2 1056
#define IV_S1 2064

__global__ void __launch_bounds__(256)
inv_fused(const float* __restrict__ filt, float* __restrict__ outg)
{
    __shared__ __align__(16) float bp3[IV_S3 + 4], bh3[IV_S3 + 4];
    __shared__ __align__(16) float bp2[IV_S2 + 4], bh2[IV_S2 + 4];
    __shared__ __align__(16) float bp1[IV_S1 + 4], bh1[IV_S1 + 4];

    const int ch = blockIdx.y, b = blockIdx.x, tid = threadIdx.x;
    const int Nout1 = 65537, Nout2 = 32769, L3n = 16385;

    const int Ta  = 2048 * b;         // lvl0 t range [Ta, Ta+2048)
    const int g1  = Ta - 7;           // prev1/hi1 buffer origin (global idx)
    const int T1a = Ta / 2 - 4;       // lvl1 first t (mult of 4)
    const int g2  = T1a - 7;          // prev2/hi2 origin
    const int T2a = 512 * b - 8;      // lvl2 first t (mult of 4)
    const int g3  = T2a - 7;          // prev3/hi3 origin

    const float* __restrict__ p3g = g_bufB + (size_t)ch * 65540;
    const float* __restrict__ h3g = g_hi + (size_t)ch * HI_STRIDE + c_HOFF[2];
    const float* __restrict__ h2g = g_hi + (size_t)ch * HI_STRIDE + c_HOFF[1];
    const float* __restrict__ h1g = g_hi + (size_t)ch * HI_STRIDE + 0;

    // ---- phase A: stage all inputs (zero-padded) ----
    for (int q = tid; q < IV_S3; q += 256) {
        const int g = g3 + q;
        const bool ok = (unsigned)g < (unsigned)L3n;
        bp3[q] = ok ? p3g[g] : 0.0f;
        bh3[q] = ok ? h3g[g] : 0.0f;
    }
    for (int q = tid; q < IV_S2; q += 256) {
        const int g = g2 + q;
        bh2[q] = ((unsigned)g < (unsigned)Nout2) ? h2g[g] : 0.0f;
    }
    for (int q = tid; q < IV_S1; q += 256) {
        const int g = g1 + q;
        bh1[q] = ((unsigned)g < (unsigned)Nout1) ? h1g[g] : 0.0f;
    }
    __syncthreads();

    ull PL[16], PH[16];

    // ---- phase B: level 2 -> prev2 buffer (133 groups of 4 t) ----
    fused_load_filters(filt, ch, 2, PL, PH);
    for (int grp = tid; grp < 133; grp += 256) {
        const int rel = 4 * grp;
        ull accp[4], acch[4];
        inv_compute4(reinterpret_cast<const float2*>(bp3 + rel),
                     reinterpret_cast<const float2*>(bh3 + rel), PL, PH, accp, acch);
        #pragma unroll
        for (int k = 0; k < 4; k++) {
            const int t = T2a + rel + k;
            ull r; add2(r, accp[k], acch[k]);
            float oe, oo; unpk2(oe, oo, r);
            const int idx = 2 * t - g2;
            if ((unsigned)idx       < (unsigned)IV_S2) bp2[idx]     = ((unsigned)(2 * t)     < (unsigned)Nout2) ? oe : 0.0f;
            if ((unsigned)(idx + 1) < (unsigned)IV_S2) bp2[idx + 1] = ((unsigned)(2 * t + 1) < (unsigned)Nout2) ? oo : 0.0f;
        }
    }
    __syncthreads();

    // ---- phase C: level 1 -> prev1 buffer (259 groups) ----
    fused_load_filters(filt, ch, 1, PL, PH);
    for (int grp = tid; grp < 259; grp += 256) {
        const int rel = 4 * grp;
        ull accp[4], acch[4];
        inv_compute4(reinterpret_cast<const float2*>(bp2 + rel),
                     reinterpret_cast<const float2*>(bh2 + rel), PL, PH, accp, acch);
        #pragma unroll
        for (int k = 0; k < 4; k++) {
            const int t = T1a + rel + k;
            ull r; add2(r, accp[k], acch[k]);
            float oe, oo; unpk2(oe, oo, r);
            const int idx = 2 * t - g1;
            if ((unsigned)idx       < (unsigned)IV_S1) bp1[idx]     = ((unsigned)(2 * t)     < (unsigned)Nout1) ? oe : 0.0f;
            if ((unsigned)(idx + 1) < (unsigned)IV_S1) bp1[idx + 1] = ((unsigned)(2 * t + 1) < (unsigned)Nout1) ? oo : 0.0f;
        }
    }
    __syncthreads();

    // ---- phase D: level 0 -> global out (512 groups, all owned/valid) ----
    fused_load_filters(filt, ch, 0, PL, PH);
    float* __restrict__ og = outg + (size_t)ch * TLEN;
    for (int grp = tid; grp < 512; grp += 256) {
        const int rel = 4 * grp;
        ull accp[4], acch[4];
        inv_compute4(reinterpret_cast<const float2*>(bp1 + rel),
                     reinterpret_cast<const float2*>(bh1 + rel), PL, PH, accp, acch);
        float o[8];
        #pragma unroll
        for (int k = 0; k < 4; k++) {
            ull r; add2(r, accp[k], acch[k]);
            unpk2(o[2 * k], o[2 * k + 1], r);
        }
        const int n = 2 * (Ta + rel);
        *reinterpret_cast<float4*>(og + n)     = make_float4(o[0], o[1], o[2], o[3]);
        *reinterpret_cast<float4*>(og + n + 4) = make_float4(o[4], o[5], o[6], o[7]);
    }
}

// ---------------------------------------------------------------------------
// Fused middle kernel (unchanged from R3): fwd 4-8 + inv 7-3 in smem.
// ---------------------------------------------------------------------------
#define OX  0
#define OY  16400
#define OH4 24608
#define OH5 32816
#define OH6 36928
#define OH7 38992
#define OH8 40032
#define SM_FLOATS 40560

__device__ __forceinline__ void fused_fwd_level(
    const float* inb, float* lob, float* hib, int Lout, int tid, const ull* W2)
{
    const float* ind = inb + 7;
    float* lod = lob + 7;
    float* hid = hib + 7;
    for (int j = tid; j < Lout; j += FNT) {
        ull acc = 0ull;
        #pragma unroll
        for (int k = 0; k < 10; k++)
            ffma2(acc, bcast2(ind[2 * j - 5 + k]), W2[k]);
        float alo, ahi;
        unpk2(alo, ahi, acc);
        lod[j] = alo;
        hid[j] = ahi;
    }
    if (tid < 7)        { lob[tid] = 0.f; hib[tid] = 0.f; }
    else if (tid < 15)  { lod[Lout + tid - 7] = 0.f; hid[Lout + tid - 7] = 0.f; }
}

__device__ __forceinline__ void fused_inv_level(
    const float* prevb, const float* hib, float* outb, int L,
    const ull* PL, const ull* PH, int tid)
{
    float* outd = outb + 7;
    const int tmax = L;
    for (int tb = 0; tb < tmax; tb += 4 * FNT) {
        const int t0 = tb + 4 * tid;
        if (t0 < tmax) {
            ull accp[4], acch[4];
            inv_compute4(reinterpret_cast<const float2*>(prevb + t0),
                         reinterpret_cast<const float2*>(hib + t0), PL, PH, accp, acch);
            #pragma unroll
            for (int k = 0; k < 4; k++) {
                if (t0 + k < tmax) {
                    ull r; add2(r, accp[k], acch[k]);
                    float oe, oo;
                    unpk2(oe, oo, r);
                    outd[2 * (t0 + k)]     = oe;
                    outd[2 * (t0 + k) + 1] = oo;
                }
            }
        }
    }
    __syncthreads();
    const int Nout = 2 * L - 1;
    if (tid < 7)       outb[tid] = 0.f;
    else if (tid < 15) outd[Nout + tid - 7] = 0.f;
}

__global__ void __launch_bounds__(FNT)
mid_kernel(const float* __restrict__ filt)
{
    extern __shared__ __align__(16) float s[];
    const int ch  = blockIdx.x;
    const int tid = threadIdx.x;

    ull W2[10];
    #pragma unroll
    for (int k = 0; k < 10; k++) W2[k] = pk2(c_WLO[k], c_WHI[k]);

    // stage lo_3 (16385 floats) from g_bufB into X
    {
        const float* __restrict__ src = g_bufB + (size_t)ch * 65540;
        float* dst = s + OX + 7;
        for (int q = 4 * tid; q + 3 < 16385; q += 4 * FNT) {
            const float4 v = *reinterpret_cast<const float4*>(src + q);
            dst[q] = v.x; dst[q + 1] = v.y; dst[q + 2] = v.z; dst[q + 3] = v.w;
        }
        if (tid == 0) dst[16384] = src[16384];
        if (tid < 7)       s[OX + tid] = 0.f;
        else if (tid < 15) dst[16385 + tid - 7] = 0.f;
    }
    __syncthreads();

    fused_fwd_level(s + OX, s + OY, s + OH4, 8193, tid, W2);  __syncthreads();
    fused_fwd_level(s + OY, s + OX, s + OH5, 4097, tid, W2);  __syncthreads();
    fused_fwd_level(s + OX, s + OY, s + OH6, 2049, tid, W2);  __syncthreads();
    fused_fwd_level(s + OY, s + OX, s + OH7, 1025, tid, W2);  __syncthreads();
    fused_fwd_level(s + OX, s + OY, s + OH8,  513, tid, W2);  __syncthreads();

    ull PL[16], PH[16];
    fused_load_filters(filt, ch, 7, PL, PH);
    fused_inv_level(s + OY, s + OH8, s + OX,  513, PL, PH, tid); __syncthreads();
    fused_load_filters(filt, ch, 6, PL, PH);
    fused_inv_level(s + OX, s + OH7, s + OY, 1025, PL, PH, tid); __syncthreads();
    fused_load_filters(filt, ch, 5, PL, PH);
    fused_inv_level(s + OY, s + OH6, s + OX, 2049, PL, PH, tid); __syncthreads();
    fused_load_filters(filt, ch, 4, PL, PH);
    fused_inv_level(s + OX, s + OH5, s + OY, 4097, PL, PH, tid); __syncthreads();

    // inverse level 3: smem -> global prev3 (g_bufB)
    fused_load_filters(filt, ch, 3, PL, PH);
    {
        const float* prevb = s + OY;
        const float* hib   = s + OH4;
        float* __restrict__ out = g_bufB + (size_t)ch * 65540;
        const int tmax = 8193, Nout = 16385;
        for (int tb = 0; tb < tmax; tb += 4 * FNT) {
            const int t0 = tb + 4 * tid;
            if (t0 >= tmax) break;
            ull accp[4], acch[4];
            inv_compute4(reinterpret_cast<const float2*>(prevb + t0),
                         reinterpret_cast<const float2*>(hib + t0), PL, PH, accp, acch);
            float o[8];
            #pragma unroll
            for (int k = 0; k < 4; k++) {
                ull r; add2(r, accp[k], acch[k]);
                unpk2(o[2 * k], o[2 * k + 1], r);
            }
            const int n0 = 2 * t0;
            if (n0 + 7 < Nout && t0 + 3 < tmax) {
                *reinterpret_cast<float4*>(out + n0)     = make_float4(o[0], o[1], o[2], o[3]);
                *reinterpret_cast<float4*>(out + n0 + 4) = make_float4(o[4], o[5], o[6], o[7]);
            } else {
                #pragma unroll
                for (int k = 0; k < 4; k++) {
                    if (t0 + k < tmax) {
                        const int n = n0 + 2 * k;
                        if (n < Nout)     out[n]     = o[2 * k];
                        if (n + 1 < Nout) out[n + 1] = o[2 * k + 1];
                    }
                }
            }
        }
    }
}

// ---------------------------------------------------------------------------
extern "C" void kernel_launch(void* const* d_in, const int* in_sizes, int n_in,
                              void* d_out, int out_size)
{
    const float* x    = (const float*)d_in[0];
    const float* filt = (const float*)d_in[1];
    if (n_in >= 2 && in_sizes[0] < in_sizes[1]) {
        x    = (const float*)d_in[1];
        filt = (const float*)d_in[0];
    }
    float* out = (float*)d_out;

    cudaFuncSetAttribute(fwd_fused, cudaFuncAttributeMaxDynamicSharedMemorySize, FW_SMEM);
    cudaFuncSetAttribute(mid_kernel, cudaFuncAttributeMaxDynamicSharedMemorySize,
                         SM_FLOATS * (int)sizeof(float));

    // fwd levels 1-3: 17 blocks cover L3 = 16385 outputs of 1024
    {
        dim3 grid(17, NCH);
        fwd_fused<<<grid, 256, FW_SMEM>>>(x);
    }
    // fwd 4-8 + inv 7-3
    mid_kernel<<<NCH, FNT, SM_FLOATS * sizeof(float)>>>(filt);
    // inv levels 2-0: 32 blocks of 4096 outputs
    {
        dim3 grid(32, NCH);
        inv_fused<<<grid, 256>>>(filt, out);
    }
}

// round 5
// speedup vs baseline: 1.3602x; 1.3602x over previous
#include <cuda_runtime.h>

// ---------------------------------------------------------------------------
// WaveletConv in 5 launches:
//   fwd12 : fwd levels 1-2 fused (halo recompute), x -> lo2 + hi1 + hi2
//   fwd3  : wide, lo2 -> lo3 + hi3
//   mid   : fwd 4-8 + inv 7-3 fused per-channel in smem (lo3 -> prev3)
//   inv2  : wide, prev3 + hi3 -> prev2
//   inv10 : inv levels 1-0 fused, prev2 + hi2 + hi1 -> out
// Packed f32x2 FMA throughout.
// ---------------------------------------------------------------------------

#define NCH      128
#define TLEN     131072
#define FNT      512    // mid kernel threads

// hi offsets padded to multiples of 4 floats (16B)
__device__ __constant__ int c_HOFF[8] = {0, 65540, 98312, 114700, 122896, 126996, 129048, 130076};
#define HI_STRIDE 130592

__device__ __constant__ float c_WLO[10] = {0.003335725285001549f, -0.012580751999015526f,
    -0.006241490213011705f, 0.07757149384006515f, -0.03224486958502952f,
    -0.24229488706619015f, 0.13842814590110342f, 0.7243085284385744f,
    0.6038292697974729f, 0.160102397974125f};
__device__ __constant__ float c_WHI[10] = {-0.160102397974125f, 0.6038292697974729f,
    -0.7243085284385744f, 0.13842814590110342f, 0.24229488706619015f,
    -0.03224486958502952f, -0.07757149384006515f, -0.006241490213011705f,
    0.012580751999015526f, 0.003335725285001549f};

// Static scratch (allocation-free rule)
__device__ __align__(16) float g_hi[NCH * HI_STRIDE];    // hi1..hi8
__device__ __align__(16) float g_bufA[NCH * 32772];      // lo2, then prev2
__device__ __align__(16) float g_bufB[NCH * 65540];      // lo3, then prev3

// ---- packed f32x2 helpers --------------------------------------------------
typedef unsigned long long ull;

__device__ __forceinline__ ull pk2(float lo, float hi) {
    ull r; asm("mov.b64 %0, {%1, %2};" : "=l"(r) : "f"(lo), "f"(hi)); return r;
}
__device__ __forceinline__ ull bcast2(float v) {
    ull r; asm("mov.b64 %0, {%1, %1};" : "=l"(r) : "f"(v)); return r;
}
__device__ __forceinline__ void ffma2(ull& d, ull a, ull b) {
    asm("fma.rn.f32x2 %0, %1, %2, %3;" : "=l"(d) : "l"(a), "l"(b), "l"(d));
}
__device__ __forceinline__ void add2(ull& d, ull a, ull b) {
    asm("add.rn.f32x2 %0, %1, %2;" : "=l"(d) : "l"(a), "l"(b));
}
__device__ __forceinline__ void unpk2(float& lo, float& hi, ull r) {
    asm("mov.b64 {%0, %1}, %2;" : "=f"(lo), "=f"(hi) : "l"(r));
}

// inverse compute: 4 consecutive t, packed even/odd outputs.
__device__ __forceinline__ void inv_compute4(const float2* sp2, const float2* sh2,
                                             const ull* PL, const ull* PH,
                                             ull* accp, ull* acch)
{
    #pragma unroll
    for (int k = 0; k < 4; k++) { accp[k] = 0ull; acch[k] = 0ull; }
    #pragma unroll
    for (int m = 0; m < 10; m++) {
        const float2 pv = sp2[m];
        const float2 hv = sh2[m];
        const ull pvx = bcast2(pv.x), pvy = bcast2(pv.y);
        const ull hvx = bcast2(hv.x), hvy = bcast2(hv.y);
        #pragma unroll
        for (int k = 0; k < 4; k++) {
            const int j0 = 2 * m - k;
            const int j1 = 2 * m + 1 - k;
            if (j0 >= 0 && j0 < 16) { ffma2(accp[k], pvx, PL[j0]); ffma2(acch[k], hvx, PH[j0]); }
            if (j1 >= 0 && j1 < 16) { ffma2(accp[k], pvy, PL[j1]); ffma2(acch[k], hvy, PH[j1]); }
        }
    }
}

__device__ __forceinline__ void fused_load_filters(
    const float* __restrict__ filt, int ch, int i, ull* PL, ull* PH)
{
    const float2* f2 = reinterpret_cast<const float2*>(filt + ((size_t)ch * 8 + (size_t)i) * 64);
    #pragma unroll
    for (int j = 0; j < 16; j++) {
        const float2 a = f2[j];
        const float2 b = f2[16 + j];
        PL[j] = pk2(a.y, a.x);
        PH[j] = pk2(b.y, b.x);
    }
}

// ---------------------------------------------------------------------------
// fwd12: levels 1+2. CTA owns lo2[c2, c2+1024); recomputes lo1 halo in smem.
// ---------------------------------------------------------------------------
#define F12_SX  4128   // >= szx = 4123
#define F12_SL1 2064   // >= sz1 = 2057
#define F12_SMEM ((F12_SX + F12_SL1) * 4)

__global__ void __launch_bounds__(256)
fwd12(const float* __restrict__ x)
{
    extern __shared__ __align__(16) float s[];
    float* SX  = s;
    float* SL1 = s + F12_SX;

    const int ch = blockIdx.y, b = blockIdx.x, tid = threadIdx.x;
    const int L1 = 65537, L2 = 32769;

    const int c2 = b * 1024;
    if (c2 >= L2) return;
    const int d2  = min(c2 + 1024, L2);
    const int a1  = 2 * c2 - 5, sz1 = 2 * (d2 - c2) + 9;
    const int ax  = 2 * a1 - 5, szx = 2 * sz1 + 9;

    const float* __restrict__ xr = x + (size_t)ch * TLEN;
    for (int q = tid; q < szx; q += 256) {
        const int g = ax + q;
        SX[q] = ((unsigned)g < (unsigned)TLEN) ? xr[g] : 0.0f;
    }
    __syncthreads();

    ull W2[10];
    #pragma unroll
    for (int k = 0; k < 10; k++) W2[k] = pk2(c_WLO[k], c_WHI[k]);

    // level 1: SX -> SL1 (lo1), hi1 -> global for owned window
    {
        float* __restrict__ hi1 = g_hi + (size_t)ch * HI_STRIDE;
        const int hlo = 2 * c2;
        const int hhi = min(2 * c2 + 2048, L1);
        const float2* SB2 = reinterpret_cast<const float2*>(SX);
        for (int q = tid; q < sz1; q += 256) {
            const int n = a1 + q;
            ull acc = 0ull;
            #pragma unroll
            for (int k = 0; k < 5; k++) {
                const float2 v = SB2[q + k];
                ffma2(acc, bcast2(v.x), W2[2 * k]);
                ffma2(acc, bcast2(v.y), W2[2 * k + 1]);
            }
            float alo, ahi; unpk2(alo, ahi, acc);
            const bool valid = (unsigned)n < (unsigned)L1;
            SL1[q] = valid ? alo : 0.0f;
            if (valid && n >= hlo && n < hhi) hi1[n] = ahi;
        }
    }
    __syncthreads();

    // level 2: SL1 -> lo2 + hi2 (global)
    {
        float* __restrict__ lo2 = g_bufA + (size_t)ch * 32772;
        float* __restrict__ hi2 = g_hi + (size_t)ch * HI_STRIDE + c_HOFF[1];
        const float2* SB2 = reinterpret_cast<const float2*>(SL1);
        for (int j = c2 + tid; j < d2; j += 256) {
            const int r = j - c2;
            ull acc = 0ull;
            #pragma unroll
            for (int k = 0; k < 5; k++) {
                const float2 v = SB2[r + k];
                ffma2(acc, bcast2(v.x), W2[2 * k]);
                ffma2(acc, bcast2(v.y), W2[2 * k + 1]);
            }
            float alo, ahi; unpk2(alo, ahi, acc);
            lo2[j] = alo;
            hi2[j] = ahi;
        }
    }
}

// ---------------------------------------------------------------------------
// fwd3: wide, lo2 -> lo3 + hi3. (R3-style wide forward kernel.)
// ---------------------------------------------------------------------------
__global__ void __launch_bounds__(256)
fwd3_kernel()
{
    __shared__ __align__(16) float s_in[2 * 2048 + 12];
    const int ch = blockIdx.y, tid = threadIdx.x;
    const int Lin = 32769, Lout = 16385;

    const float* __restrict__ in  = g_bufA + (size_t)ch * 32772;
    float* __restrict__ lo3 = g_bufB + (size_t)ch * 65540;
    float* __restrict__ hi3 = g_hi + (size_t)ch * HI_STRIDE + c_HOFF[2];

    const int j0 = blockIdx.x * 2048;
    if (j0 >= Lout) return;
    const int jend = min(j0 + 2048, Lout);
    const int base = 2 * j0 - 5;
    const int cnt  = 2 * (jend - j0) + 9;

    for (int q = tid; q < cnt; q += 256) {
        const int idx = base + q;
        s_in[q] = ((unsigned)idx < (unsigned)Lin) ? in[idx] : 0.0f;
    }
    __syncthreads();

    ull W2[10];
    #pragma unroll
    for (int k = 0; k < 10; k++) W2[k] = pk2(c_WLO[k], c_WHI[k]);

    const float2* s2 = reinterpret_cast<const float2*>(s_in);
    for (int j = j0 + tid; j < jend; j += 256) {
        const int jj = j - j0;
        ull acc = 0ull;
        #pragma unroll
        for (int k = 0; k < 5; k++) {
            const float2 v = s2[jj + k];
            ffma2(acc, bcast2(v.x), W2[2 * k]);
            ffma2(acc, bcast2(v.y), W2[2 * k + 1]);
        }
        float alo, ahi; unpk2(alo, ahi, acc);
        lo3[j] = alo;
        hi3[j] = ahi;
    }
}

// ---------------------------------------------------------------------------
// inv2: wide, prev3 + hi3 -> prev2 (R3-style wide inverse kernel).
// ---------------------------------------------------------------------------
__global__ void __launch_bounds__(256)
inv2_kernel(const float* __restrict__ filt)
{
    __shared__ __align__(16) float s_prev[1024 + 24];
    __shared__ __align__(16) float s_hi[1024 + 24];

    const int ch = blockIdx.y, tid = threadIdx.x;
    const int L = 16385, Nout = 32769, tmax = 16385;

    const float* __restrict__ prev = g_bufB + (size_t)ch * 65540;
    const float* __restrict__ hv   = g_hi + (size_t)ch * HI_STRIDE + c_HOFF[2];
    float* __restrict__ out = g_bufA + (size_t)ch * 32772;

    const int tc0 = blockIdx.x * 1024;
    if (tc0 >= tmax) return;
    const int tc1   = min(tc0 + 1024, tmax);
    const int mbase = tc0 - 7;
    const int cnt   = (tc1 - tc0) + 20;

    for (int q = tid; q < cnt; q += 256) {
        const int m  = mbase + q;
        const bool ok = (unsigned)m < (unsigned)L;
        s_prev[q] = ok ? prev[m] : 0.0f;
        s_hi[q]   = ok ? hv[m]   : 0.0f;
    }

    ull PL[16], PH[16];
    fused_load_filters(filt, ch, 2, PL, PH);
    __syncthreads();

    const int p  = 4 * tid;
    const int t0 = tc0 + p;
    if (t0 >= tmax) return;

    ull accp[4], acch[4];
    inv_compute4(reinterpret_cast<const float2*>(s_prev + p),
                 reinterpret_cast<const float2*>(s_hi + p), PL, PH, accp, acch);

    float o[8];
    #pragma unroll
    for (int k = 0; k < 4; k++) {
        ull r; add2(r, accp[k], acch[k]);
        unpk2(o[2 * k], o[2 * k + 1], r);
    }
    const int n0 = 2 * t0;
    if (n0 + 7 < Nout && t0 + 3 < tmax) {
        *reinterpret_cast<float4*>(out + n0)     = make_float4(o[0], o[1], o[2], o[3]);
        *reinterpret_cast<float4*>(out + n0 + 4) = make_float4(o[4], o[5], o[6], o[7]);
    } else {
        #pragma unroll
        for (int k = 0; k < 4; k++) {
            if (t0 + k < tmax) {
                const int n = n0 + 2 * k;
                if (n < Nout)     out[n]     = o[2 * k];
                if (n + 1 < Nout) out[n + 1] = o[2 * k + 1];
            }
        }
    }
}

// ---------------------------------------------------------------------------
// inv10: levels 1+0 fused. CTA owns 1024 level-0 t values (2048 outputs).
// ---------------------------------------------------------------------------
__global__ void __launch_bounds__(256)
inv10(const float* __restrict__ filt, float* __restrict__ outg)
{
    __shared__ __align__(16) float bp2s[544], bh2s[544];
    __shared__ __align__(16) float bh1s[1040];
    __shared__ __align__(16) float bp1s[1048];

    const int ch = blockIdx.y, b = blockIdx.x, tid = threadIdx.x;
    const int Nout1 = 65537, Nout2 = 32769;

    const int Ta  = 1024 * b;       // level-0 t range [Ta, Ta+1024)
    const int g1  = Ta - 7;         // prev1/hi1 buffer origin
    const int T1a = 512 * b - 4;    // level-1 first t (mult of 4)
    const int g2  = T1a - 7;        // prev2/hi2 buffer origin

    const float* __restrict__ p2g = g_bufA + (size_t)ch * 32772;
    const float* __restrict__ h2g = g_hi + (size_t)ch * HI_STRIDE + c_HOFF[1];
    const float* __restrict__ h1g = g_hi + (size_t)ch * HI_STRIDE;

    // stage inputs (zero-padded)
    for (int q = tid; q < 540; q += 256) {
        const int g = g2 + q;
        const bool ok = (unsigned)g < (unsigned)Nout2;
        bp2s[q] = ok ? p2g[g] : 0.0f;
        bh2s[q] = ok ? h2g[g] : 0.0f;
    }
    for (int q = tid; q < 1040; q += 256) {
        const int g = g1 + q;
        bh1s[q] = ((unsigned)g < (unsigned)Nout1) ? h1g[g] : 0.0f;
    }

    ull PL[16], PH[16];
    fused_load_filters(filt, ch, 1, PL, PH);
    __syncthreads();

    // level 1: 131 groups of 4 t -> bp1s (masked vs Nout1)
    if (tid < 131) {
        const int rel = 4 * tid;
        ull accp[4], acch[4];
        inv_compute4(reinterpret_cast<const float2*>(bp2s + rel),
                     reinterpret_cast<const float2*>(bh2s + rel), PL, PH, accp, acch);
        #pragma unroll
        for (int k = 0; k < 4; k++) {
            const int t = T1a + rel + k;
            ull r; add2(r, accp[k], acch[k]);
            float oe, oo; unpk2(oe, oo, r);
            const int idx = 2 * t - g1;
            if ((unsigned)idx       < 1040u) bp1s[idx]     = ((unsigned)(2 * t)     < (unsigned)Nout1) ? oe : 0.0f;
            if ((unsigned)(idx + 1) < 1040u) bp1s[idx + 1] = ((unsigned)(2 * t + 1) < (unsigned)Nout1) ? oo : 0.0f;
        }
    }
    fused_load_filters(filt, ch, 0, PL, PH);
    __syncthreads();

    // level 0: exactly 1 group per thread, all outputs valid
    {
        const int rel = 4 * tid;
        ull accp[4], acch[4];
        inv_compute4(reinterpret_cast<const float2*>(bp1s + rel),
                     reinterpret_cast<const float2*>(bh1s + rel), PL, PH, accp, acch);
        float o[8];
        #pragma unroll
        for (int k = 0; k < 4; k++) {
            ull r; add2(r, accp[k], acch[k]);
            unpk2(o[2 * k], o[2 * k + 1], r);
        }
        float* __restrict__ og = outg + (size_t)ch * TLEN;
        const int n = 2 * (Ta + rel);
        *reinterpret_cast<float4*>(og + n)     = make_float4(o[0], o[1], o[2], o[3]);
        *reinterpret_cast<float4*>(og + n + 4) = make_float4(o[4], o[5], o[6], o[7]);
    }
}

// ---------------------------------------------------------------------------
// mid_kernel (unchanged, proven): fwd 4-8 + inv 7-3 in smem.
// ---------------------------------------------------------------------------
#define OX  0
#define OY  16400
#define OH4 24608
#define OH5 32816
#define OH6 36928
#define OH7 38992
#define OH8 40032
#define SM_FLOATS 40560

__device__ __forceinline__ void fused_fwd_level(
    const float* inb, float* lob, float* hib, int Lout, int tid, const ull* W2)
{
    const float* ind = inb + 7;
    float* lod = lob + 7;
    float* hid = hib + 7;
    for (int j = tid; j < Lout; j += FNT) {
        ull acc = 0ull;
        #pragma unroll
        for (int k = 0; k < 10; k++)
            ffma2(acc, bcast2(ind[2 * j - 5 + k]), W2[k]);
        float alo, ahi;
        unpk2(alo, ahi, acc);
        lod[j] = alo;
        hid[j] = ahi;
    }
    if (tid < 7)        { lob[tid] = 0.f; hib[tid] = 0.f; }
    else if (tid < 15)  { lod[Lout + tid - 7] = 0.f; hid[Lout + tid - 7] = 0.f; }
}

__device__ __forceinline__ void fused_inv_level(
    const float* prevb, const float* hib, float* outb, int L,
    const ull* PL, const ull* PH, int tid)
{
    float* outd = outb + 7;
    const int tmax = L;
    for (int tb = 0; tb < tmax; tb += 4 * FNT) {
        const int t0 = tb + 4 * tid;
        if (t0 < tmax) {
            ull accp[4], acch[4];
            inv_compute4(reinterpret_cast<const float2*>(prevb + t0),
                         reinterpret_cast<const float2*>(hib + t0), PL, PH, accp, acch);
            #pragma unroll
            for (int k = 0; k < 4; k++) {
                if (t0 + k < tmax) {
                    ull r; add2(r, accp[k], acch[k]);
                    float oe, oo;
                    unpk2(oe, oo, r);
                    outd[2 * (t0 + k)]     = oe;
                    outd[2 * (t0 + k) + 1] = oo;
                }
            }
        }
    }
    __syncthreads();
    const int Nout = 2 * L - 1;
    if (tid < 7)       outb[tid] = 0.f;
    else if (tid < 15) outd[Nout + tid - 7] = 0.f;
}

__global__ void __launch_bounds__(FNT)
mid_kernel(const float* __restrict__ filt)
{
    extern __shared__ __align__(16) float s[];
    const int ch  = blockIdx.x;
    const int tid = threadIdx.x;

    ull W2[10];
    #pragma unroll
    for (int k = 0; k < 10; k++) W2[k] = pk2(c_WLO[k], c_WHI[k]);

    // stage lo_3 (16385 floats) from g_bufB into X
    {
        const float* __restrict__ src = g_bufB + (size_t)ch * 65540;
        float* dst = s + OX + 7;
        for (int q = 4 * tid; q + 3 < 16385; q += 4 * FNT) {
            const float4 v = *reinterpret_cast<const float4*>(src + q);
            dst[q] = v.x; dst[q + 1] = v.y; dst[q + 2] = v.z; dst[q + 3] = v.w;
        }
        if (tid == 0) dst[16384] = src[16384];
        if (tid < 7)       s[OX + tid] = 0.f;
        else if (tid < 15) dst[16385 + tid - 7] = 0.f;
    }
    __syncthreads();

    fused_fwd_level(s + OX, s + OY, s + OH4, 8193, tid, W2);  __syncthreads();
    fused_fwd_level(s + OY, s + OX, s + OH5, 4097, tid, W2);  __syncthreads();
    fused_fwd_level(s + OX, s + OY, s + OH6, 2049, tid, W2);  __syncthreads();
    fused_fwd_level(s + OY, s + OX, s + OH7, 1025, tid, W2);  __syncthreads();
    fused_fwd_level(s + OX, s + OY, s + OH8,  513, tid, W2);  __syncthreads();

    ull PL[16], PH[16];
    fused_load_filters(filt, ch, 7, PL, PH);
    fused_inv_level(s + OY, s + OH8, s + OX,  513, PL, PH, tid); __syncthreads();
    fused_load_filters(filt, ch, 6, PL, PH);
    fused_inv_level(s + OX, s + OH7, s + OY, 1025, PL, PH, tid); __syncthreads();
    fused_load_filters(filt, ch, 5, PL, PH);
    fused_inv_level(s + OY, s + OH6, s + OX, 2049, PL, PH, tid); __syncthreads();
    fused_load_filters(filt, ch, 4, PL, PH);
    fused_inv_level(s + OX, s + OH5, s + OY, 4097, PL, PH, tid); __syncthreads();

    // inverse level 3: smem -> global prev3 (g_bufB)
    fused_load_filters(filt, ch, 3, PL, PH);
    {
        const float* prevb = s + OY;
        const float* hib   = s + OH4;
        float* __restrict__ out = g_bufB + (size_t)ch * 65540;
        const int tmax = 8193, Nout = 16385;
        for (int tb = 0; tb < tmax; tb += 4 * FNT) {
            const int t0 = tb + 4 * tid;
            if (t0 >= tmax) break;
            ull accp[4], acch[4];
            inv_compute4(reinterpret_cast<const float2*>(prevb + t0),
                         reinterpret_cast<const float2*>(hib + t0), PL, PH, accp, acch);
            float o[8];
            #pragma unroll
            for (int k = 0; k < 4; k++) {
                ull r; add2(r, accp[k], acch[k]);
                unpk2(o[2 * k], o[2 * k + 1], r);
            }
            const int n0 = 2 * t0;
            if (n0 + 7 < Nout && t0 + 3 < tmax) {
                *reinterpret_cast<float4*>(out + n0)     = make_float4(o[0], o[1], o[2], o[3]);
                *reinterpret_cast<float4*>(out + n0 + 4) = make_float4(o[4], o[5], o[6], o[7]);
            } else {
                #pragma unroll
                for (int k = 0; k < 4; k++) {
                    if (t0 + k < tmax) {
                        const int n = n0 + 2 * k;
                        if (n < Nout)     out[n]     = o[2 * k];
                        if (n + 1 < Nout) out[n + 1] = o[2 * k + 1];
                    }
                }
            }
        }
    }
}

// ---------------------------------------------------------------------------
extern "C" void kernel_launch(void* const* d_in, const int* in_sizes, int n_in,
                              void* d_out, int out_size)
{
    const float* x    = (const float*)d_in[0];
    const float* filt = (const float*)d_in[1];
    if (n_in >= 2 && in_sizes[0] < in_sizes[1]) {
        x    = (const float*)d_in[1];
        filt = (const float*)d_in[0];
    }
    float* out = (float*)d_out;

    cudaFuncSetAttribute(mid_kernel, cudaFuncAttributeMaxDynamicSharedMemorySize,
                         SM_FLOATS * (int)sizeof(float));

    // fwd levels 1+2: 33 blocks of 1024 lo2 outputs
    {
        dim3 grid(33, NCH);
        fwd12<<<grid, 256, F12_SMEM>>>(x);
    }
    // fwd level 3: 9 blocks of 2048
    {
        dim3 grid(9, NCH);
        fwd3_kernel<<<grid, 256>>>();
    }
    // fwd 4-8 + inv 7-3
    mid_kernel<<<NCH, FNT, SM_FLOATS * sizeof(float)>>>(filt);
    // inv level 2: 17 blocks of 1024 t
    {
        dim3 grid(17, NCH);
        inv2_kernel<<<grid, 256>>>(filt);
    }
    // inv levels 1+0: 64 blocks of 1024 t
    {
        dim3 grid(64, NCH);
        inv10<<<grid, 256>>>(filt, out);
    }
}